// round 3
// baseline (speedup 1.0000x reference)
#include <cuda_runtime.h>
#include <math_constants.h>

#define BB 512
#define TT 512
#define KK 64

// 16.7 MB history scratch (argmax index per (b, t, j)), plus per-batch best-last tag.
__device__ unsigned char g_hist[(size_t)BB * TT * KK];
__device__ int g_best[BB];

// ---------------------------------------------------------------------------
// Forward Viterbi: one block per batch, thread j owns next-tag j.
//   score double-buffered in shared; trans column in registers.
//   history idx written to g_hist; best-last tag to g_best.
// Exactly replicates reference arithmetic: cand = (score[i] + trans[i][j]) + emit[j],
// argmax = first (lowest i) maximum, masked steps freeze score but still record idx.
// ---------------------------------------------------------------------------
__global__ __launch_bounds__(KK, 8) void viterbi_forward(
    const float* __restrict__ emissions,   // [B, T, K]
    const int*   __restrict__ mask,        // [B, T]
    const float* __restrict__ start_t,     // [K]
    const float* __restrict__ end_t,       // [K]
    const float* __restrict__ trans)       // [K, K]
{
    const int b = blockIdx.x;
    const int j = threadIdx.x;

    __shared__ __align__(16) float sbuf[2][KK];

    // Transition column trans[:, j] -> registers (coalesced loads across threads).
    float tcol[KK];
#pragma unroll
    for (int i = 0; i < KK; ++i) tcol[i] = trans[i * KK + j];

    const float* em = emissions + (size_t)b * TT * KK;
    const int*   mk = mask + b * TT;

    // t = 0 init: score0 = start + emissions[:,0]
    float score = start_t[j] + em[j];
    sbuf[0][j] = score;

    // prefetch step t=1
    float e = em[KK + j];
    int   m = mk[1];
    __syncthreads();

    int p = 0;
    for (int t = 1; t < TT; ++t) {
        // software prefetch next step's emit + mask
        float e_nxt = 0.0f;
        int   m_nxt = 0;
        if (t + 1 < TT) {
            e_nxt = em[(t + 1) * KK + j];
            m_nxt = mk[t + 1];
        }

        const float4* s4 = (const float4*)sbuf[p];

        // 4 parallel argmax chains (chunks of 16 i's) to break the serial
        // compare->select dependency. First-index tie semantics preserved:
        // within a chunk: strict > ascending; across chunks: strict > from
        // higher chunk (lower chunk wins ties).
        float bst[4];
        int   bid[4];
#pragma unroll
        for (int c = 0; c < 4; ++c) { bst[c] = -CUDART_INF_F; bid[c] = 0; }

#pragma unroll
        for (int q = 0; q < 16; ++q) {
            const float4 s = s4[q];
            const int c = q >> 2;
            {
                float v = (s.x + tcol[4 * q + 0]) + e;
                if (v > bst[c]) { bst[c] = v; bid[c] = 4 * q + 0; }
            }
            {
                float v = (s.y + tcol[4 * q + 1]) + e;
                if (v > bst[c]) { bst[c] = v; bid[c] = 4 * q + 1; }
            }
            {
                float v = (s.z + tcol[4 * q + 2]) + e;
                if (v > bst[c]) { bst[c] = v; bid[c] = 4 * q + 2; }
            }
            {
                float v = (s.w + tcol[4 * q + 3]) + e;
                if (v > bst[c]) { bst[c] = v; bid[c] = 4 * q + 3; }
            }
        }

        float bv = bst[0];
        int   bi = bid[0];
#pragma unroll
        for (int c = 1; c < 4; ++c) {
            if (bst[c] > bv) { bv = bst[c]; bi = bid[c]; }
        }

        // history always records the computed argmax (reference semantics);
        // mask only gates the score update.
        g_hist[((size_t)b * TT + t) * KK + j] = (unsigned char)bi;

        const float ns = m ? bv : score;
        score = ns;
        sbuf[p ^ 1][j] = ns;
        __syncthreads();
        p ^= 1;
        e = e_nxt;
        m = m_nxt;
    }

    // final: add end_transitions, block-wide first-index argmax
    sbuf[p][j] = score + end_t[j];
    __syncthreads();
    if (j == 0) {
        float bv = sbuf[p][0];
        int   bi = 0;
#pragma unroll
        for (int i = 1; i < KK; ++i) {
            if (sbuf[p][i] > bv) { bv = sbuf[p][i]; bi = i; }
        }
        g_best[b] = bi;
    }
}

// ---------------------------------------------------------------------------
// Backtrace: one block per batch. Stage the 32KB history slab + mask into
// shared, then one thread walks the dependent chain at LDS latency.
// Output tags written as FLOAT32 (harness output dtype).
// ---------------------------------------------------------------------------
__global__ __launch_bounds__(256) void viterbi_backtrace(
    const int*  __restrict__ mask,   // [B, T]
    float*      __restrict__ out)    // [B, T] float32 tags
{
    const int b = blockIdx.x;
    __shared__ unsigned char h[TT * KK];   // 32 KB
    __shared__ int msk[TT];                // 2 KB

    const uint4* src = (const uint4*)(g_hist + (size_t)b * TT * KK);
    uint4* dst = (uint4*)h;
#pragma unroll 4
    for (int k = threadIdx.x; k < (TT * KK) / 16; k += blockDim.x)
        dst[k] = src[k];
    for (int t = threadIdx.x; t < TT; t += blockDim.x)
        msk[t] = mask[b * TT + t];
    __syncthreads();

    if (threadIdx.x == 0) {
        int tag = g_best[b];
        out[b * TT + (TT - 1)] = (float)tag;
        for (int t = TT - 1; t >= 1; --t) {
            const int prev = h[t * KK + tag];
            tag = msk[t] ? prev : tag;
            out[b * TT + t - 1] = (float)tag;
        }
    }
}

extern "C" void kernel_launch(void* const* d_in, const int* in_sizes, int n_in,
                              void* d_out, int out_size)
{
    // Bind inputs by element count (robust to any same-size-order-preserving
    // permutation of metadata order):
    //   16777216 -> emissions [512,512,64] f32
    //     262144 -> attn_mask [512,512]    i32
    //       4096 -> transitions [64,64]    f32
    //         64 -> start_transitions (first), end_transitions (second)
    const float* emissions = nullptr;
    const int*   attn_mask = nullptr;
    const float* start_t   = nullptr;
    const float* end_t     = nullptr;
    const float* trans     = nullptr;

    for (int i = 0; i < n_in; ++i) {
        const int sz = in_sizes[i];
        if (sz == BB * TT * KK)      emissions = (const float*)d_in[i];
        else if (sz == BB * TT)      attn_mask = (const int*)d_in[i];
        else if (sz == KK * KK)      trans     = (const float*)d_in[i];
        else if (sz == KK) {
            if (!start_t) start_t = (const float*)d_in[i];
            else          end_t   = (const float*)d_in[i];
        }
    }

    float* out = (float*)d_out;  // [512,512] float32 tag values

    viterbi_forward<<<BB, KK>>>(emissions, attn_mask, start_t, end_t, trans);
    viterbi_backtrace<<<BB, 256>>>(attn_mask, out);
}